// round 5
// baseline (speedup 1.0000x reference)
#include <cuda_runtime.h>
#include <cstdint>
#include <cstddef>

#define SEQ   2048
#define BATCH 128
#define HID   256
#define NCTA  128   // 64 clusters * 2 CTAs

// ---------------- f32x2 packed helpers (sm_103a) ----------------
__device__ __forceinline__ unsigned long long pk2(float x, float y){
    unsigned long long r; asm("mov.b64 %0, {%1,%2};" : "=l"(r) : "f"(x), "f"(y)); return r;
}
__device__ __forceinline__ void upk2(unsigned long long v, float& x, float& y){
    asm("mov.b64 {%0,%1}, %2;" : "=f"(x), "=f"(y) : "l"(v));
}
__device__ __forceinline__ unsigned long long ffma2(unsigned long long a,
                                                    unsigned long long b,
                                                    unsigned long long c){
    unsigned long long d;
    asm("fma.rn.f32x2 %0, %1, %2, %3;" : "=l"(d) : "l"(a), "l"(b), "l"(c));
    return d;
}

// ---------------- smem / cluster helpers ----------------
__device__ __forceinline__ unsigned smem_u32(const void* p){
    return (unsigned)__cvta_generic_to_shared(p);
}
__device__ __forceinline__ void mbar_init(unsigned a, unsigned cnt){
    asm volatile("mbarrier.init.shared.b64 [%0], %1;" :: "r"(a), "r"(cnt) : "memory");
}
__device__ __forceinline__ void mbar_inval(unsigned a){
    asm volatile("mbarrier.inval.shared.b64 [%0];" :: "r"(a) : "memory");
}
__device__ __forceinline__ void st_remote_f(unsigned laddr, unsigned peer, float v){
    unsigned r;
    asm volatile("mapa.shared::cluster.u32 %0, %1, %2;" : "=r"(r) : "r"(laddr), "r"(peer));
    asm volatile("st.shared::cluster.b32 [%0], %1;" :: "r"(r), "f"(v) : "memory");
}
__device__ __forceinline__ void arrive_remote(unsigned mbar_laddr, unsigned peer){
    unsigned r;
    asm volatile("mapa.shared::cluster.u32 %0, %1, %2;" : "=r"(r) : "r"(mbar_laddr), "r"(peer));
    asm volatile("mbarrier.arrive.release.cluster.shared::cluster.b64 _, [%0];"
                 :: "r"(r) : "memory");
}
__device__ __forceinline__ void mbar_wait_acq_cluster(unsigned a, unsigned parity){
    asm volatile(
        "{\n\t.reg .pred P;\n\t"
        "WL_%=:\n\t"
        "mbarrier.try_wait.parity.acquire.cluster.shared.b64 P, [%0], %1, 0x989680;\n\t"
        "@!P bra WL_%=;\n\t"
        "}"
        :: "r"(a), "r"(parity) : "memory");
}
__device__ __forceinline__ void cluster_sync_hw(){
    asm volatile("barrier.cluster.arrive.aligned;" ::: "memory");
    asm volatile("barrier.cluster.wait.aligned;"   ::: "memory");
}
__device__ __forceinline__ unsigned cta_rank(){
    unsigned r; asm("mov.u32 %0, %%cluster_ctarank;" : "=r"(r)); return r;
}

// =====================================================================
// Persistent RNN kernel: 64 clusters x 2 CTAs, 2 batch rows per cluster.
// Each CTA holds a 128x256 half of W_eff register-resident (128 regs/thr).
// Thread t: iloc = t&127 (output row within half), jseg = t>>7 (j half).
// =====================================================================
__global__ void __cluster_dims__(2,1,1) __launch_bounds__(256,1)
rnn_kernel(const float* __restrict__ x,      // (SEQ, BATCH)
           const float* __restrict__ h0,     // (BATCH, HID)
           const float* __restrict__ W_ih,   // (HID, 1)
           const float* __restrict__ W_hh,   // (HID, HID)
           const float* __restrict__ W_hhb,  // (HID, HID)
           const float* __restrict__ b_h,    // (HID,)
           const void*  __restrict__ ctxp,   // scalar (int or float)
           float* __restrict__ outbuf)       // (BATCH, SEQ, HID)
{
    __shared__ __align__(16) float sa[2][2][HID];     // [buf][batch][j]  4 KB
    __shared__ __align__(16) float2 part[2][128];     // [jseg][iloc]     2 KB
    __shared__ float sx[SEQ * 2];                     // x[t][b0..b1]     16 KB
    __shared__ __align__(8) unsigned long long mbar[2];

    const int t    = (int)threadIdx.x;
    const unsigned rank = cta_rank();
    const unsigned peer = rank ^ 1u;
    const int cid  = (int)blockIdx.x >> 1;
    const int b0   = cid * 2;
    const int b1   = b0 + 1;
    const int iloc = t & 127;
    const int jseg = t >> 7;
    const int ibase = (int)rank << 7;
    const int iglob = ibase + iloc;
    const int jb   = jseg << 7;

    // context: stored as int32 or float32 — handle both (both encode 1 -> 1.0f)
    float ctx;
    {
        int   iv = *(const int*)ctxp;
        float fv = *(const float*)ctxp;
        ctx = (iv >= -1000000 && iv <= 1000000) ? (float)iv : fv;
    }

    // ---- load W_eff half into registers, packed f32x2 along j ----
    unsigned long long wreg[64];
    {
        const float4* wh = reinterpret_cast<const float4*>(W_hh  + (size_t)iglob * HID + jb);
        const float4* wb = reinterpret_cast<const float4*>(W_hhb + (size_t)iglob * HID + jb);
        #pragma unroll
        for (int m = 0; m < 32; ++m){
            float4 a4 = wh[m];
            float4 c4 = wb[m];
            wreg[2*m]   = pk2(fmaf(ctx, c4.x, a4.x), fmaf(ctx, c4.y, a4.y));
            wreg[2*m+1] = pk2(fmaf(ctx, c4.z, a4.z), fmaf(ctx, c4.w, a4.w));
        }
    }

    const float win_r = W_ih[iglob];
    const float bh_r  = b_h[iglob];

    // ---- preload x columns for b0/b1 into smem ----
    for (int idx = t; idx < SEQ * 2; idx += 256){
        int tt = idx >> 1, bb = idx & 1;
        sx[idx] = x[(size_t)tt * BATCH + b0 + bb];
    }
    // ---- init activation buffer 0 from h0 (both halves, no exchange) ----
    {
        int j = t;  // 256 threads, HID = 256
        sa[0][0][j] = fmaf(2.f, h0[(size_t)b0 * HID + j], -1.f);
        sa[0][1][j] = fmaf(2.f, h0[(size_t)b1 * HID + j], -1.f);
    }
    if (t == 0){
        mbar_init(smem_u32(&mbar[0]), 128);
        mbar_init(smem_u32(&mbar[1]), 128);
    }
    __syncthreads();
    cluster_sync_hw();   // mbar init + buffers visible cluster-wide

    float* outp0 = outbuf + (size_t)b0 * SEQ * HID;
    float* outp1 = outbuf + (size_t)b1 * SEQ * HID;

    const unsigned sa_u32   = smem_u32(&sa[0][0][0]);
    const unsigned mbar_u32 = smem_u32(&mbar[0]);
    const bool iwait = (jseg != (int)rank);   // my j-half is produced by the peer
    int ph[2] = {0, 0};
    int cur = 0;

    for (int step = 0; step < SEQ; ++step){
        const int nxt = cur ^ 1;

        // ---- matvec partials over my j-half, both batches, f32x2-packed ----
        const ulonglong2* a0p = reinterpret_cast<const ulonglong2*>(&sa[cur][0][jb]);
        const ulonglong2* a1p = reinterpret_cast<const ulonglong2*>(&sa[cur][1][jb]);
        unsigned long long acc00 = 0ull, acc01 = 0ull, acc10 = 0ull, acc11 = 0ull;
        #pragma unroll
        for (int m = 0; m < 32; ++m){
            ulonglong2 A0 = a0p[m];
            ulonglong2 A1 = a1p[m];
            acc00 = ffma2(wreg[2*m],   A0.x, acc00);
            acc01 = ffma2(wreg[2*m+1], A0.y, acc01);
            acc10 = ffma2(wreg[2*m],   A1.x, acc10);
            acc11 = ffma2(wreg[2*m+1], A1.y, acc11);
        }
        float s0a, s0b, s0c, s0d, s1a, s1b, s1c, s1d;
        upk2(acc00, s0a, s0b); upk2(acc01, s0c, s0d);
        upk2(acc10, s1a, s1b); upk2(acc11, s1c, s1d);
        part[jseg][iloc] = make_float2((s0a + s0b) + (s0c + s0d),
                                       (s1a + s1b) + (s1c + s1d));
        __syncthreads();   // B1: partials ready; everyone done reading sa[cur]

        if (t < 128){
            float2 pA = part[0][t];
            float2 pB = part[1][t];
            float xv0 = sx[2*step + 0];
            float xv1 = sx[2*step + 1];
            float pre0 = pA.x + pB.x + fmaf(xv0, win_r, bh_r);
            float pre1 = pA.y + pB.y + fmaf(xv1, win_r, bh_r);
            float h0v = __fdividef(1.f, 1.f + __expf(-pre0));
            float h1v = __fdividef(1.f, 1.f + __expf(-pre1));
            outp0[(size_t)step * HID + iglob] = h0v;
            outp1[(size_t)step * HID + iglob] = h1v;
            float a0 = fmaf(2.f, h0v, -1.f);
            float a1 = fmaf(2.f, h1v, -1.f);
            sa[nxt][0][iglob] = a0;
            sa[nxt][1][iglob] = a1;
            // deliver my half to the peer's buffer nxt
            unsigned l0 = sa_u32 + (unsigned)(((nxt*2 + 0)*HID + iglob) * 4);
            unsigned l1 = sa_u32 + (unsigned)(((nxt*2 + 1)*HID + iglob) * 4);
            st_remote_f(l0, peer, a0);
            st_remote_f(l1, peer, a1);
            arrive_remote(mbar_u32 + (unsigned)(nxt * 8), peer);  // release orders my stores
        }
        __syncthreads();   // B2: local half of sa[nxt] visible; part free for reuse

        if (iwait){
            mbar_wait_acq_cluster(mbar_u32 + (unsigned)(nxt * 8), (unsigned)ph[nxt]);
            ph[nxt] ^= 1;
        }
        cur = nxt;
    }

    cluster_sync_hw();   // no CTA exits while peer may still write our smem
    if (t == 0){ mbar_inval(smem_u32(&mbar[0])); mbar_inval(smem_u32(&mbar[1])); }
}

// =====================================================================
// y[b,t] = out[b,t,:] . W[0,:] + b[0]   (one warp per (b,t) row)
// =====================================================================
__global__ void __launch_bounds__(256)
y_kernel(const float* __restrict__ outbuf,  // (BATCH, SEQ, HID)
         const float* __restrict__ W,       // (2, HID) -> row 0
         const float* __restrict__ bb,      // (2,)
         float* __restrict__ y)             // (BATCH, SEQ)
{
    int row  = (int)blockIdx.x * 8 + ((int)threadIdx.x >> 5);
    int lane = (int)threadIdx.x & 31;
    const float4* p  = reinterpret_cast<const float4*>(outbuf + (size_t)row * HID);
    const float4* wp = reinterpret_cast<const float4*>(W);
    float4 a = p[lane*2],  b4 = p[lane*2 + 1];
    float4 u = wp[lane*2], v  = wp[lane*2 + 1];
    float s = a.x*u.x + a.y*u.y + a.z*u.z + a.w*u.w
            + b4.x*v.x + b4.y*v.y + b4.z*v.z + b4.w*v.w;
    #pragma unroll
    for (int off = 16; off; off >>= 1) s += __shfl_xor_sync(0xFFFFFFFFu, s, off);
    if (lane == 0) y[row] = s + bb[0];
}

extern "C" void kernel_launch(void* const* d_in, const int* in_sizes, int n_in,
                              void* d_out, int out_size)
{
    const float* x     = (const float*)d_in[0];
    const float* h0    = (const float*)d_in[1];
    const float* W_ih  = (const float*)d_in[2];
    const float* W_hh  = (const float*)d_in[3];
    const float* W_hhb = (const float*)d_in[4];
    const float* b_h   = (const float*)d_in[5];
    const float* W     = (const float*)d_in[6];
    const float* b     = (const float*)d_in[7];
    const void*  ctx   = d_in[8];

    float* y      = (float*)d_out;                       // (BATCH, SEQ)
    float* outbuf = y + (size_t)BATCH * SEQ;             // (BATCH, SEQ, HID)

    rnn_kernel<<<NCTA, 256>>>(x, h0, W_ih, W_hh, W_hhb, b_h, ctx, outbuf);
    y_kernel<<<(BATCH * SEQ) / 8, 256>>>(outbuf, W, b, y);
}